// round 1
// baseline (speedup 1.0000x reference)
#include <cuda_runtime.h>
#include <math.h>

#define NN 100000
#define EE 1600000
#define FH 64      // input/hidden width
#define CC 40      // output classes

// ---------------- scratch (device globals; no allocation allowed) ----------
__device__ float g_invo[NN];          // out-degree -> inv sqrt
__device__ float g_invi[NN];          // in-degree  -> inv sqrt
__device__ float g_w[EE];             // per-edge weight
__device__ float g_p[(size_t)NN * FH];   // GEMM output (reused all layers)
__device__ float g_y[(size_t)NN * FH];   // SpMM output layer 1
__device__ float g_o[(size_t)NN * CC];   // SpMM output layer 3 (pre-logsoftmax)

// ---------------- degree / weight kernels ----------------------------------
__global__ void zero_deg_kernel() {
    int i = blockIdx.x * blockDim.x + threadIdx.x;
    if (i < NN) { g_invo[i] = 0.f; g_invi[i] = 0.f; }
}

__global__ void deg_kernel(const int* __restrict__ row, const int* __restrict__ col) {
    int e = blockIdx.x * blockDim.x + threadIdx.x;
    if (e < EE) {
        atomicAdd(&g_invo[row[e]], 1.f);
        atomicAdd(&g_invi[col[e]], 1.f);
    }
}

__global__ void inv_kernel() {
    int i = blockIdx.x * blockDim.x + threadIdx.x;
    if (i < NN) {
        float o = g_invo[i], n = g_invi[i];
        g_invo[i] = (o > 0.f) ? rsqrtf(o) : 0.f;
        g_invi[i] = (n > 0.f) ? rsqrtf(n) : 0.f;
    }
}

__global__ void ew_kernel(const int* __restrict__ row, const int* __restrict__ col) {
    int e = blockIdx.x * blockDim.x + threadIdx.x;
    if (e < EE) g_w[e] = g_invo[row[e]] * g_invi[col[e]];
}

// ---------------- dense GEMM: P[N,OUT] = (relu?)X[N,64] @ W[64,OUT] --------
// Each thread owns one output column (W column cached in registers, reused
// across all nodes of the block). X rows staged in smem, broadcast-read.
template <int OUT, int YD, int TILES, bool RELU>
__global__ void gemm_kernel(const float* __restrict__ X,
                            const float* __restrict__ W,
                            float* __restrict__ P) {
    __shared__ float sX[YD][FH];
    const int tx = threadIdx.x;            // 0..OUT-1
    const int ty = threadIdx.y;            // 0..YD-1
    const int tid = ty * OUT + tx;
    const int nthreads = OUT * YD;

    float wr[FH];
#pragma unroll
    for (int k = 0; k < FH; k++) wr[k] = W[k * OUT + tx];

    const int base = blockIdx.x * (YD * TILES);
#pragma unroll 1
    for (int t = 0; t < TILES; t++) {
        const int nb = base + t * YD;
        for (int idx = tid; idx < YD * FH; idx += nthreads) {
            int r = idx >> 6, c = idx & 63;
            int n = nb + r;
            float v = (n < NN) ? X[(size_t)n * FH + c] : 0.f;
            if (RELU) v = fmaxf(v, 0.f);
            sX[r][c] = v;
        }
        __syncthreads();
        const int n = nb + ty;
        if (n < NN) {
            float a0 = 0.f, a1 = 0.f;
#pragma unroll
            for (int k = 0; k < FH; k += 2) {
                a0 = fmaf(sX[ty][k],     wr[k],     a0);
                a1 = fmaf(sX[ty][k + 1], wr[k + 1], a1);
            }
            P[(size_t)n * OUT + tx] = a0 + a1;
        }
        __syncthreads();
    }
}

// ---------------- bias init --------------------------------------------------
template <int OUT>
__global__ void init_bias_kernel(float* __restrict__ Y, const float* __restrict__ B) {
    int idx = blockIdx.x * blockDim.x + threadIdx.x;
    if (idx < NN * OUT) Y[idx] = B[idx % OUT];
}

// ---------------- SpMM scatter: Y[row] += w[e] * P[col]  (atomic) ----------
template <int OUT>
__global__ void spmm_kernel(const int* __restrict__ row, const int* __restrict__ col,
                            const float* __restrict__ P, float* __restrict__ Y) {
    const int TPE = OUT / 4;               // threads per edge (float4 each)
    int gid = blockIdx.x * blockDim.x + threadIdx.x;
    int e = gid / TPE;
    if (e >= EE) return;
    int q = (gid % TPE) * 4;
    int r = row[e], c = col[e];
    float wv = g_w[e];
    const float4 v = *reinterpret_cast<const float4*>(P + (size_t)c * OUT + q);
    float* dst = Y + (size_t)r * OUT + q;
    atomicAdd(dst + 0, wv * v.x);
    atomicAdd(dst + 1, wv * v.y);
    atomicAdd(dst + 2, wv * v.z);
    atomicAdd(dst + 3, wv * v.w);
}

// ---------------- log-softmax over 40 classes, one warp per row -------------
__global__ void lsm_kernel(const float* __restrict__ X, float* __restrict__ O) {
    int r = (blockIdx.x * blockDim.x + threadIdx.x) >> 5;
    int lane = threadIdx.x & 31;
    if (r >= NN) return;
    const float* xr = X + (size_t)r * CC;
    float v0 = xr[lane];                                    // lane < 32 < 40 always valid
    float v1 = (lane + 32 < CC) ? xr[lane + 32] : -INFINITY;
    float m = fmaxf(v0, v1);
#pragma unroll
    for (int o = 16; o; o >>= 1) m = fmaxf(m, __shfl_xor_sync(0xffffffffu, m, o));
    float s = expf(v0 - m) + ((lane + 32 < CC) ? expf(v1 - m) : 0.f);
#pragma unroll
    for (int o = 16; o; o >>= 1) s += __shfl_xor_sync(0xffffffffu, s, o);
    float ls = m + logf(s);
    O[(size_t)r * CC + lane] = v0 - ls;
    if (lane + 32 < CC) O[(size_t)r * CC + lane + 32] = v1 - ls;
}

// ---------------- launch -----------------------------------------------------
extern "C" void kernel_launch(void* const* d_in, const int* in_sizes, int n_in,
                              void* d_out, int out_size) {
    const float* x   = (const float*)d_in[0];
    const int*   ei  = (const int*)d_in[1];
    const int*   rowp = ei;
    const int*   colp = ei + EE;
    const float* W1s = (const float*)d_in[2];
    const float* b1s = (const float*)d_in[3];
    const float* W2s = (const float*)d_in[6];
    const float* b2s = (const float*)d_in[7];
    const float* Wos = (const float*)d_in[10];
    const float* bos = (const float*)d_in[11];

    float* out = (float*)d_out;
    float* h   = out;                       // [N, 64]
    float* lsm = out + (size_t)NN * FH;     // [N, 40]

    float *pw, *pp, *py, *po;
    cudaGetSymbolAddress((void**)&pw, g_w);
    cudaGetSymbolAddress((void**)&pp, g_p);
    cudaGetSymbolAddress((void**)&py, g_y);
    cudaGetSymbolAddress((void**)&po, g_o);
    (void)pw;

    const int T = 256;

    // degrees + edge weights (recomputed every call — determinism rule)
    zero_deg_kernel<<<(NN + T - 1) / T, T>>>();
    deg_kernel<<<(EE + T - 1) / T, T>>>(rowp, colp);
    inv_kernel<<<(NN + T - 1) / T, T>>>();
    ew_kernel<<<(EE + T - 1) / T, T>>>(rowp, colp);

    // ---- layer 1: x0 = A @ (x @ W1s) + b1s ----
    {
        const int NPB = 4 * 16;
        gemm_kernel<FH, 4, 16, false><<<(NN + NPB - 1) / NPB, dim3(FH, 4)>>>(x, W1s, pp);
        init_bias_kernel<FH><<<(NN * FH + T - 1) / T, T>>>(py, b1s);
        int work = EE * (FH / 4);
        spmm_kernel<FH><<<(work + T - 1) / T, T>>>(rowp, colp, pp, py);
    }
    // ---- layer 2: h = A @ (relu(x0) @ W2s) + b2s  (h -> d_out) ----
    {
        const int NPB = 4 * 16;
        gemm_kernel<FH, 4, 16, true><<<(NN + NPB - 1) / NPB, dim3(FH, 4)>>>(py, W2s, pp);
        init_bias_kernel<FH><<<(NN * FH + T - 1) / T, T>>>(h, b2s);
        int work = EE * (FH / 4);
        spmm_kernel<FH><<<(work + T - 1) / T, T>>>(rowp, colp, pp, h);
    }
    // ---- layer 3: out = A @ (relu(h) @ Wos) + bos ; then log_softmax ----
    {
        const int NPB = 6 * 8;
        gemm_kernel<CC, 6, 8, true><<<(NN + NPB - 1) / NPB, dim3(CC, 6)>>>(h, Wos, pp);
        init_bias_kernel<CC><<<(NN * CC + T - 1) / T, T>>>(po, bos);
        int work = EE * (CC / 4);
        spmm_kernel<CC><<<(work + T - 1) / T, T>>>(rowp, colp, pp, po);
        lsm_kernel<<<((NN * 32) + T - 1) / T, T>>>(po, lsm);
    }
}

// round 2
// speedup vs baseline: 2.2877x; 2.2877x over previous
#include <cuda_runtime.h>
#include <math.h>

#define NN 100000
#define EE 1600000
#define FH 64      // input/hidden width
#define CC 40      // output classes

// ---------------- scratch (device globals; no allocation allowed) ----------
__device__ int   g_deg_out[NN];
__device__ int   g_deg_in[NN];
__device__ float g_invo[NN];
__device__ float g_invi[NN];
__device__ int   g_start[NN];            // CSR row start
__device__ int   g_pos[NN];              // bump cursor per row
__device__ uint2 g_csr[EE];              // .x = col, .y = weight bits
__device__ unsigned int g_ctr;           // global bump counter
__device__ float g_p[(size_t)NN * FH];   // GEMM output (reused all layers)
__device__ float g_y[(size_t)NN * FH];   // SpMM output layer 1

// ---------------- zero -------------------------------------------------------
__global__ void zero_kernel() {
    int i = blockIdx.x * blockDim.x + threadIdx.x;
    if (i < NN) { g_deg_out[i] = 0; g_deg_in[i] = 0; }
    if (i == 0) g_ctr = 0u;
}

// ---------------- degree histogram ------------------------------------------
__global__ void hist_kernel(const int* __restrict__ row, const int* __restrict__ col) {
    int e = blockIdx.x * blockDim.x + threadIdx.x;
    if (e < EE) {
        atomicAdd(&g_deg_out[row[e]], 1);
        atomicAdd(&g_deg_in[col[e]], 1);
    }
}

// ---------------- range assignment (warp-aggregated bump alloc) + inv degs --
__global__ void ranges_kernel() {
    int i = blockIdx.x * blockDim.x + threadIdx.x;
    int lane = threadIdx.x & 31;
    int d = (i < NN) ? g_deg_out[i] : 0;
    // warp inclusive scan of d
    int incl = d;
#pragma unroll
    for (int o = 1; o < 32; o <<= 1) {
        int v = __shfl_up_sync(0xffffffffu, incl, o);
        if (lane >= o) incl += v;
    }
    int total = __shfl_sync(0xffffffffu, incl, 31);
    unsigned int base = 0;
    if (lane == 31) base = atomicAdd(&g_ctr, (unsigned int)total);
    base = __shfl_sync(0xffffffffu, base, 31);
    if (i < NN) {
        int st = (int)base + (incl - d);
        g_start[i] = st;
        g_pos[i]   = st;
        int di = g_deg_in[i];
        g_invo[i] = (d  > 0) ? rsqrtf((float)d)  : 0.f;
        g_invi[i] = (di > 0) ? rsqrtf((float)di) : 0.f;
    }
}

// ---------------- edge scatter into CSR --------------------------------------
__global__ void scatter_kernel(const int* __restrict__ row, const int* __restrict__ col) {
    int e = blockIdx.x * blockDim.x + threadIdx.x;
    if (e >= EE) return;
    int r = row[e], c = col[e];
    int p = atomicAdd(&g_pos[r], 1);
    float w = g_invo[r] * g_invi[c];
    g_csr[p] = make_uint2((unsigned int)c, __float_as_uint(w));
}

// ---------------- dense GEMM: P[N,OUT] = (relu?)X[N,64] @ W[64,OUT] ----------
template <int OUT, int YD, int TILES, bool RELU>
__global__ void gemm_kernel(const float* __restrict__ X,
                            const float* __restrict__ W,
                            float* __restrict__ P) {
    __shared__ float sX[YD][FH];
    const int tx = threadIdx.x;            // 0..OUT-1
    const int ty = threadIdx.y;            // 0..YD-1
    const int tid = ty * OUT + tx;
    const int nthreads = OUT * YD;

    float wr[FH];
#pragma unroll
    for (int k = 0; k < FH; k++) wr[k] = W[k * OUT + tx];

    const int base = blockIdx.x * (YD * TILES);
#pragma unroll 1
    for (int t = 0; t < TILES; t++) {
        const int nb = base + t * YD;
        for (int idx = tid; idx < YD * FH; idx += nthreads) {
            int r = idx >> 6, c = idx & 63;
            int n = nb + r;
            float v = (n < NN) ? X[(size_t)n * FH + c] : 0.f;
            if (RELU) v = fmaxf(v, 0.f);
            sX[r][c] = v;
        }
        __syncthreads();
        const int n = nb + ty;
        if (n < NN) {
            float a0 = 0.f, a1 = 0.f;
#pragma unroll
            for (int k = 0; k < FH; k += 2) {
                a0 = fmaf(sX[ty][k],     wr[k],     a0);
                a1 = fmaf(sX[ty][k + 1], wr[k + 1], a1);
            }
            P[(size_t)n * OUT + tx] = a0 + a1;
        }
        __syncthreads();
    }
}

// ---------------- gather SpMM, width 64: one warp per node -------------------
__global__ void spmm64_kernel(const float* __restrict__ P,
                              const float* __restrict__ bias,
                              float* __restrict__ Y) {
    int n = (blockIdx.x * blockDim.x + threadIdx.x) >> 5;
    int lane = threadIdx.x & 31;
    if (n >= NN) return;
    int s = g_start[n];
    int d = g_deg_out[n];
    float a0 = bias[lane], a1 = bias[lane + 32];
    const uint2* cw = g_csr + s;
    int e = 0;
    for (; e + 2 <= d; e += 2) {
        uint2 p0 = cw[e];
        uint2 p1 = cw[e + 1];
        const float* r0 = P + (size_t)p0.x * FH;
        const float* r1 = P + (size_t)p1.x * FH;
        float w0 = __uint_as_float(p0.y);
        float w1 = __uint_as_float(p1.y);
        float x0a = __ldg(r0 + lane), x0b = __ldg(r0 + lane + 32);
        float x1a = __ldg(r1 + lane), x1b = __ldg(r1 + lane + 32);
        a0 = fmaf(w0, x0a, a0); a1 = fmaf(w0, x0b, a1);
        a0 = fmaf(w1, x1a, a0); a1 = fmaf(w1, x1b, a1);
    }
    if (e < d) {
        uint2 p0 = cw[e];
        const float* r0 = P + (size_t)p0.x * FH;
        float w0 = __uint_as_float(p0.y);
        a0 = fmaf(w0, __ldg(r0 + lane), a0);
        a1 = fmaf(w0, __ldg(r0 + lane + 32), a1);
    }
    Y[(size_t)n * FH + lane]      = a0;
    Y[(size_t)n * FH + lane + 32] = a1;
}

// ---------------- gather SpMM width 40 + fused log-softmax -------------------
__global__ void spmm40_lsm_kernel(const float* __restrict__ P,
                                  const float* __restrict__ bias,
                                  float* __restrict__ O) {
    int n = (blockIdx.x * blockDim.x + threadIdx.x) >> 5;
    int lane = threadIdx.x & 31;
    if (n >= NN) return;
    int s = g_start[n];
    int d = g_deg_out[n];
    const bool hi = (lane < CC - 32);  // lanes 0..7 own features 32..39
    float a0 = bias[lane];
    float a1 = hi ? bias[lane + 32] : 0.f;
    const uint2* cw = g_csr + s;
    int e = 0;
    for (; e + 2 <= d; e += 2) {
        uint2 p0 = cw[e];
        uint2 p1 = cw[e + 1];
        const float* r0 = P + (size_t)p0.x * CC;
        const float* r1 = P + (size_t)p1.x * CC;
        float w0 = __uint_as_float(p0.y);
        float w1 = __uint_as_float(p1.y);
        float x0a = __ldg(r0 + lane);
        float x1a = __ldg(r1 + lane);
        float x0b = hi ? __ldg(r0 + lane + 32) : 0.f;
        float x1b = hi ? __ldg(r1 + lane + 32) : 0.f;
        a0 = fmaf(w0, x0a, a0); a1 = fmaf(w0, x0b, a1);
        a0 = fmaf(w1, x1a, a0); a1 = fmaf(w1, x1b, a1);
    }
    if (e < d) {
        uint2 p0 = cw[e];
        const float* r0 = P + (size_t)p0.x * CC;
        float w0 = __uint_as_float(p0.y);
        a0 = fmaf(w0, __ldg(r0 + lane), a0);
        if (hi) a1 = fmaf(w0, __ldg(r0 + lane + 32), a1);
    }
    // fused log-softmax over 40 values
    float m = fmaxf(a0, hi ? a1 : -INFINITY);
#pragma unroll
    for (int o = 16; o; o >>= 1) m = fmaxf(m, __shfl_xor_sync(0xffffffffu, m, o));
    float sum = expf(a0 - m) + (hi ? expf(a1 - m) : 0.f);
#pragma unroll
    for (int o = 16; o; o >>= 1) sum += __shfl_xor_sync(0xffffffffu, sum, o);
    float ls = m + logf(sum);
    O[(size_t)n * CC + lane] = a0 - ls;
    if (hi) O[(size_t)n * CC + lane + 32] = a1 - ls;
}

// ---------------- launch -----------------------------------------------------
extern "C" void kernel_launch(void* const* d_in, const int* in_sizes, int n_in,
                              void* d_out, int out_size) {
    const float* x   = (const float*)d_in[0];
    const int*   ei  = (const int*)d_in[1];
    const int*   rowp = ei;
    const int*   colp = ei + EE;
    const float* W1s = (const float*)d_in[2];
    const float* b1s = (const float*)d_in[3];
    const float* W2s = (const float*)d_in[6];
    const float* b2s = (const float*)d_in[7];
    const float* Wos = (const float*)d_in[10];
    const float* bos = (const float*)d_in[11];

    float* out = (float*)d_out;
    float* h   = out;                       // [N, 64]
    float* lsm = out + (size_t)NN * FH;     // [N, 40]

    float *pp, *py;
    cudaGetSymbolAddress((void**)&pp, g_p);
    cudaGetSymbolAddress((void**)&py, g_y);

    const int T = 256;

    // ---- CSR build (recomputed every call — determinism rule) ----
    zero_kernel<<<(NN + T - 1) / T, T>>>();
    hist_kernel<<<(EE + T - 1) / T, T>>>(rowp, colp);
    ranges_kernel<<<(NN + T - 1) / T, T>>>();
    scatter_kernel<<<(EE + T - 1) / T, T>>>(rowp, colp);

    const int WARPS_GRID = (NN * 32 + T - 1) / T;

    // ---- layer 1: x0 = A @ (x @ W1s) + b1s ----
    {
        const int NPB = 4 * 16;
        gemm_kernel<FH, 4, 16, false><<<(NN + NPB - 1) / NPB, dim3(FH, 4)>>>(x, W1s, pp);
        spmm64_kernel<<<WARPS_GRID, T>>>(pp, b1s, py);
    }
    // ---- layer 2: h = A @ (relu(x0) @ W2s) + b2s  (h -> d_out) ----
    {
        const int NPB = 4 * 16;
        gemm_kernel<FH, 4, 16, true><<<(NN + NPB - 1) / NPB, dim3(FH, 4)>>>(py, W2s, pp);
        spmm64_kernel<<<WARPS_GRID, T>>>(pp, b2s, h);
    }
    // ---- layer 3: out = log_softmax(A @ (relu(h) @ Wos) + bos) ----
    {
        const int NPB = 6 * 8;
        gemm_kernel<CC, 6, 8, true><<<(NN + NPB - 1) / NPB, dim3(CC, 6)>>>(h, Wos, pp);
        spmm40_lsm_kernel<<<WARPS_GRID, T>>>(pp, bos, lsm);
    }
}

// round 3
// speedup vs baseline: 2.4334x; 1.0637x over previous
#include <cuda_runtime.h>
#include <cuda_fp16.h>
#include <math.h>

#define NN 100000
#define EE 1600000
#define FH 64      // input/hidden width
#define CC 40      // output classes

// ---------------- scratch (device globals; no allocation allowed) ----------
__device__ int   g_deg_out[NN];
__device__ int   g_deg_in[NN];
__device__ float g_invo[NN];
__device__ float g_invi[NN];
__device__ int   g_start[NN];              // CSR row start
__device__ int   g_pos[NN];                // bump cursor per row
__device__ uint2 g_csr[EE];                // .x = col, .y = weight bits
__device__ unsigned int g_ctr;             // global bump counter
__device__ __half2 g_p[(size_t)NN * (FH / 2)];  // fp16 GEMM output (gathered by SpMM)
__device__ float g_y[(size_t)NN * FH];     // SpMM output layer 1

// ---------------- zero -------------------------------------------------------
__global__ void zero_kernel() {
    int i = blockIdx.x * blockDim.x + threadIdx.x;
    if (i < NN) { g_deg_out[i] = 0; g_deg_in[i] = 0; }
    if (i == 0) g_ctr = 0u;
}

// ---------------- degree histogram ------------------------------------------
__global__ void hist_kernel(const int* __restrict__ row, const int* __restrict__ col) {
    int e = blockIdx.x * blockDim.x + threadIdx.x;
    if (e < EE) {
        atomicAdd(&g_deg_out[row[e]], 1);
        atomicAdd(&g_deg_in[col[e]], 1);
    }
}

// ---------------- range assignment (warp-aggregated bump alloc) + inv degs --
__global__ void ranges_kernel() {
    int i = blockIdx.x * blockDim.x + threadIdx.x;
    int lane = threadIdx.x & 31;
    int d = (i < NN) ? g_deg_out[i] : 0;
    int incl = d;
#pragma unroll
    for (int o = 1; o < 32; o <<= 1) {
        int v = __shfl_up_sync(0xffffffffu, incl, o);
        if (lane >= o) incl += v;
    }
    int total = __shfl_sync(0xffffffffu, incl, 31);
    unsigned int base = 0;
    if (lane == 31) base = atomicAdd(&g_ctr, (unsigned int)total);
    base = __shfl_sync(0xffffffffu, base, 31);
    if (i < NN) {
        int st = (int)base + (incl - d);
        g_start[i] = st;
        g_pos[i]   = st;
        int di = g_deg_in[i];
        g_invo[i] = (d  > 0) ? rsqrtf((float)d)  : 0.f;
        g_invi[i] = (di > 0) ? rsqrtf((float)di) : 0.f;
    }
}

// ---------------- edge scatter into CSR --------------------------------------
__global__ void scatter_kernel(const int* __restrict__ row, const int* __restrict__ col) {
    int e = blockIdx.x * blockDim.x + threadIdx.x;
    if (e >= EE) return;
    int r = row[e], c = col[e];
    int p = atomicAdd(&g_pos[r], 1);
    float w = g_invo[r] * g_invi[c];
    g_csr[p] = make_uint2((unsigned int)c, __float_as_uint(w));
}

// ---------------- dense GEMM: P[N,OUT](fp16) = (relu?)X[N,64] @ W[64,OUT] ----
template <int OUT, int YD, int TILES, bool RELU>
__global__ void gemm_kernel(const float* __restrict__ X,
                            const float* __restrict__ W,
                            __half* __restrict__ P) {
    __shared__ float sX[YD][FH];
    const int tx = threadIdx.x;            // 0..OUT-1
    const int ty = threadIdx.y;            // 0..YD-1
    const int tid = ty * OUT + tx;
    const int nthreads = OUT * YD;

    float wr[FH];
#pragma unroll
    for (int k = 0; k < FH; k++) wr[k] = W[k * OUT + tx];

    const int base = blockIdx.x * (YD * TILES);
#pragma unroll 1
    for (int t = 0; t < TILES; t++) {
        const int nb = base + t * YD;
        for (int idx = tid; idx < YD * FH; idx += nthreads) {
            int r = idx >> 6, c = idx & 63;
            int n = nb + r;
            float v = (n < NN) ? X[(size_t)n * FH + c] : 0.f;
            if (RELU) v = fmaxf(v, 0.f);
            sX[r][c] = v;
        }
        __syncthreads();
        const int n = nb + ty;
        if (n < NN) {
            float a0 = 0.f, a1 = 0.f;
#pragma unroll
            for (int k = 0; k < FH; k += 2) {
                a0 = fmaf(sX[ty][k],     wr[k],     a0);
                a1 = fmaf(sX[ty][k + 1], wr[k + 1], a1);
            }
            P[(size_t)n * OUT + tx] = __float2half(a0 + a1);
        }
        __syncthreads();
    }
}

// ---------------- gather SpMM, width 64 (fp16 rows): one warp per node -------
__global__ void spmm64_kernel(const __half2* __restrict__ P,
                              const float* __restrict__ bias,
                              float* __restrict__ Y) {
    int n = (blockIdx.x * blockDim.x + threadIdx.x) >> 5;
    int lane = threadIdx.x & 31;
    if (n >= NN) return;
    int s = g_start[n];
    int d = g_deg_out[n];
    float a0 = bias[2 * lane], a1 = bias[2 * lane + 1];
    const uint2* cw = g_csr + s;
    int e = 0;
    for (; e + 4 <= d; e += 4) {
        uint2 p0 = cw[e], p1 = cw[e + 1], p2 = cw[e + 2], p3 = cw[e + 3];
        float2 v0 = __half22float2(__ldg(P + (size_t)p0.x * (FH / 2) + lane));
        float2 v1 = __half22float2(__ldg(P + (size_t)p1.x * (FH / 2) + lane));
        float2 v2 = __half22float2(__ldg(P + (size_t)p2.x * (FH / 2) + lane));
        float2 v3 = __half22float2(__ldg(P + (size_t)p3.x * (FH / 2) + lane));
        float w0 = __uint_as_float(p0.y), w1 = __uint_as_float(p1.y);
        float w2 = __uint_as_float(p2.y), w3 = __uint_as_float(p3.y);
        a0 = fmaf(w0, v0.x, a0); a1 = fmaf(w0, v0.y, a1);
        a0 = fmaf(w1, v1.x, a0); a1 = fmaf(w1, v1.y, a1);
        a0 = fmaf(w2, v2.x, a0); a1 = fmaf(w2, v2.y, a1);
        a0 = fmaf(w3, v3.x, a0); a1 = fmaf(w3, v3.y, a1);
    }
    for (; e < d; e++) {
        uint2 p0 = cw[e];
        float2 v0 = __half22float2(__ldg(P + (size_t)p0.x * (FH / 2) + lane));
        float w0 = __uint_as_float(p0.y);
        a0 = fmaf(w0, v0.x, a0); a1 = fmaf(w0, v0.y, a1);
    }
    *reinterpret_cast<float2*>(Y + (size_t)n * FH + 2 * lane) = make_float2(a0, a1);
}

// ---------------- gather SpMM width 40 (fp16 rows) + fused log-softmax -------
__global__ void spmm40_lsm_kernel(const __half2* __restrict__ P,
                                  const float* __restrict__ bias,
                                  float* __restrict__ O) {
    int n = (blockIdx.x * blockDim.x + threadIdx.x) >> 5;
    int lane = threadIdx.x & 31;
    if (n >= NN) return;
    int s = g_start[n];
    int d = g_deg_out[n];
    const bool act = (lane < CC / 2);   // lanes 0..19 own feature pairs
    float a0 = act ? bias[2 * lane] : 0.f;
    float a1 = act ? bias[2 * lane + 1] : 0.f;
    const uint2* cw = g_csr + s;
    int e = 0;
    for (; e + 2 <= d; e += 2) {
        uint2 p0 = cw[e], p1 = cw[e + 1];
        float2 v0 = act ? __half22float2(__ldg(P + (size_t)p0.x * (CC / 2) + lane))
                        : make_float2(0.f, 0.f);
        float2 v1 = act ? __half22float2(__ldg(P + (size_t)p1.x * (CC / 2) + lane))
                        : make_float2(0.f, 0.f);
        float w0 = __uint_as_float(p0.y), w1 = __uint_as_float(p1.y);
        a0 = fmaf(w0, v0.x, a0); a1 = fmaf(w0, v0.y, a1);
        a0 = fmaf(w1, v1.x, a0); a1 = fmaf(w1, v1.y, a1);
    }
    if (e < d) {
        uint2 p0 = cw[e];
        if (act) {
            float2 v0 = __half22float2(__ldg(P + (size_t)p0.x * (CC / 2) + lane));
            float w0 = __uint_as_float(p0.y);
            a0 = fmaf(w0, v0.x, a0); a1 = fmaf(w0, v0.y, a1);
        }
    }
    // fused log-softmax over 40 values
    float m = act ? fmaxf(a0, a1) : -INFINITY;
#pragma unroll
    for (int o = 16; o; o >>= 1) m = fmaxf(m, __shfl_xor_sync(0xffffffffu, m, o));
    float sum = act ? (expf(a0 - m) + expf(a1 - m)) : 0.f;
#pragma unroll
    for (int o = 16; o; o >>= 1) sum += __shfl_xor_sync(0xffffffffu, sum, o);
    float ls = m + logf(sum);
    if (act) {
        *reinterpret_cast<float2*>(O + (size_t)n * CC + 2 * lane) =
            make_float2(a0 - ls, a1 - ls);
    }
}

// ---------------- launch -----------------------------------------------------
extern "C" void kernel_launch(void* const* d_in, const int* in_sizes, int n_in,
                              void* d_out, int out_size) {
    const float* x   = (const float*)d_in[0];
    const int*   ei  = (const int*)d_in[1];
    const int*   rowp = ei;
    const int*   colp = ei + EE;
    const float* W1s = (const float*)d_in[2];
    const float* b1s = (const float*)d_in[3];
    const float* W2s = (const float*)d_in[6];
    const float* b2s = (const float*)d_in[7];
    const float* Wos = (const float*)d_in[10];
    const float* bos = (const float*)d_in[11];

    float* out = (float*)d_out;
    float* h   = out;                       // [N, 64]
    float* lsm = out + (size_t)NN * FH;     // [N, 40]

    __half2* pp;
    float* py;
    cudaGetSymbolAddress((void**)&pp, g_p);
    cudaGetSymbolAddress((void**)&py, g_y);

    const int T = 256;

    // ---- CSR build (recomputed every call — determinism rule) ----
    zero_kernel<<<(NN + T - 1) / T, T>>>();
    hist_kernel<<<(EE + T - 1) / T, T>>>(rowp, colp);
    ranges_kernel<<<(NN + T - 1) / T, T>>>();
    scatter_kernel<<<(EE + T - 1) / T, T>>>(rowp, colp);

    const int WARPS_GRID = (NN * 32 + T - 1) / T;

    // ---- layer 1: x0 = A @ (x @ W1s) + b1s ----
    {
        const int NPB = 4 * 16;
        gemm_kernel<FH, 4, 16, false><<<(NN + NPB - 1) / NPB, dim3(FH, 4)>>>(x, W1s, (__half*)pp);
        spmm64_kernel<<<WARPS_GRID, T>>>(pp, b1s, py);
    }
    // ---- layer 2: h = A @ (relu(x0) @ W2s) + b2s  (h -> d_out) ----
    {
        const int NPB = 4 * 16;
        gemm_kernel<FH, 4, 16, true><<<(NN + NPB - 1) / NPB, dim3(FH, 4)>>>(py, W2s, (__half*)pp);
        spmm64_kernel<<<WARPS_GRID, T>>>(pp, b2s, h);
    }
    // ---- layer 3: out = log_softmax(A @ (relu(h) @ Wos) + bos) ----
    {
        const int NPB = 6 * 8;
        gemm_kernel<CC, 6, 8, true><<<(NN + NPB - 1) / NPB, dim3(CC, 6)>>>(h, Wos, (__half*)pp);
        spmm40_lsm_kernel<<<WARPS_GRID, T>>>(pp, bos, lsm);
    }
}